// round 12
// baseline (speedup 1.0000x reference)
#include <cuda_runtime.h>
#include <cuda_bf16.h>
#include <math.h>
#include <cstdint>

#define BB 32
#define MM 1024
#define NN 1024

typedef unsigned long long u64;
typedef unsigned int u32;
typedef unsigned short u16;

// ---------------- scratch (no allocations allowed) ----------------
__device__ u32   gPu[BB * MM * 32];   // P rows: 64 bf16 = 32 u32 per row (4MB)
__device__ u32   gQu[BB * NN * 32];   // Q rows (4MB)
__device__ float g_part[2][BB * MM];  // per n-half sqrt-sums
__device__ float g_dish[BB * MM];
__device__ float g_lpart[256];
__device__ int   g_which[BB];
__device__ float g_Rbest[BB][12];

// ---------------- helpers ----------------
__device__ __forceinline__ u32 smem_u32(const void* p) {
    u32 a; asm("{ .reg .u64 t; cvta.to.shared.u64 t, %1; cvt.u32.u64 %0, t; }" : "=r"(a) : "l"(p));
    return a;
}
__device__ __forceinline__ float sqrt_approx(float x) {
    float r; asm("sqrt.approx.f32 %0, %1;" : "=f"(r) : "f"(x)); return r;
}
__device__ __forceinline__ void mma16816(float& d0, float& d1, float& d2, float& d3,
                                         u32 a0, u32 a1, u32 a2, u32 a3, u32 b0, u32 b1) {
    asm volatile(
        "mma.sync.aligned.m16n8k16.row.col.f32.bf16.bf16.f32 "
        "{%0,%1,%2,%3}, {%4,%5,%6,%7}, {%8,%9}, {%0,%1,%2,%3};"
        : "+f"(d0), "+f"(d1), "+f"(d2), "+f"(d3)
        : "r"(a0), "r"(a1), "r"(a2), "r"(a3), "r"(b0), "r"(b1));
}
__device__ __forceinline__ void ldsm_x4(u32& r0, u32& r1, u32& r2, u32& r3, u32 addr) {
    asm volatile("ldmatrix.sync.aligned.m8n8.x4.shared.b16 {%0,%1,%2,%3}, [%4];"
                 : "=r"(r0), "=r"(r1), "=r"(r2), "=r"(r3) : "r"(addr));
}
__device__ __forceinline__ void ldsm_x2(u32& r0, u32& r1, u32 addr) {
    asm volatile("ldmatrix.sync.aligned.m8n8.x2.shared.b16 {%0,%1}, [%2];"
                 : "=r"(r0), "=r"(r1) : "r"(addr));
}
__device__ __forceinline__ void split_bf16(float v, u16& h, u16& l) {
    __nv_bfloat16 hb = __float2bfloat16(v);
    float r = v - __bfloat162float(hb);
    __nv_bfloat16 lb = __float2bfloat16(r);
    h = __bfloat16_as_ushort(hb);
    l = __bfloat16_as_ushort(lb);
}

// quat (xyzw) + t -> 12 floats: R row-major then t
__device__ __forceinline__ void quat_to_Rt(float qx, float qy, float qz, float qw,
                                           float t0, float t1, float t2, float* o) {
    float nrm = sqrtf(qx * qx + qy * qy + qz * qz + qw * qw);
    float inv = __fdividef(1.0f, nrm + 1e-8f);
    qx *= inv; qy *= inv; qz *= inv; qw *= inv;
    o[0] = 1.0f - 2.0f * (qy * qy + qz * qz);
    o[1] = 2.0f * (qx * qy - qz * qw);
    o[2] = 2.0f * (qx * qz + qy * qw);
    o[3] = 2.0f * (qx * qy + qz * qw);
    o[4] = 1.0f - 2.0f * (qx * qx + qz * qz);
    o[5] = 2.0f * (qy * qz - qx * qw);
    o[6] = 2.0f * (qx * qz - qy * qw);
    o[7] = 2.0f * (qy * qz + qx * qw);
    o[8] = 1.0f - 2.0f * (qx * qx + qy * qy);
    o[9] = t0; o[10] = t1; o[11] = t2;
}

// ---------------- K0: build P/Q bf16-split rows ----------------
// dis^2[m,n] = P[m,:].Q[n,:] over K=51 (pad 64):
//   P17 = [|t|^2, 1, -2t, 2Rt, -2R_ij];  Q17 = [1, |mp|^2+|tg|^2, tg, mp, mp_i*tg_j]
// split: P cols = [h,h,l], Q cols = [h,l,h]  (drops lo*lo, keeps 3-product compensation)
__global__ void k_prep(const float* __restrict__ pred_r,
                       const float* __restrict__ pred_t,
                       const float* __restrict__ points,
                       const float* __restrict__ mp,
                       const float* __restrict__ tg) {
    __shared__ u32 stage[128 * 33];
    int t = threadIdx.x;
    int i = blockIdx.x * 128 + t;   // 256 blocks x 128 = 32768 rows

    // ---- P row ----
    {
        float4 q = reinterpret_cast<const float4*>(pred_r)[i];
        float t0 = points[3 * i + 0] + pred_t[3 * i + 0];
        float t1 = points[3 * i + 1] + pred_t[3 * i + 1];
        float t2 = points[3 * i + 2] + pred_t[3 * i + 2];
        float o[12];
        quat_to_Rt(q.x, q.y, q.z, q.w, t0, t1, t2, o);
        float w0 = o[0] * t0 + o[1] * t1 + o[2] * t2;
        float w1 = o[3] * t0 + o[4] * t1 + o[5] * t2;
        float w2 = o[6] * t0 + o[7] * t1 + o[8] * t2;
        float P[17];
        P[0] = t0 * t0 + t1 * t1 + t2 * t2;
        P[1] = 1.0f;
        P[2] = -2.0f * t0; P[3] = -2.0f * t1; P[4] = -2.0f * t2;
        P[5] = 2.0f * w0;  P[6] = 2.0f * w1;  P[7] = 2.0f * w2;
        #pragma unroll
        for (int u = 0; u < 9; u++) P[8 + u] = -2.0f * o[u];

        u16 col[64];
        #pragma unroll
        for (int k = 0; k < 64; k++) col[k] = 0;
        #pragma unroll
        for (int k = 0; k < 17; k++) {
            u16 h, l; split_bf16(P[k], h, l);
            col[k] = h; col[17 + k] = h; col[34 + k] = l;
        }
        #pragma unroll
        for (int j = 0; j < 32; j++)
            stage[t * 33 + j] = (u32)col[2 * j] | ((u32)col[2 * j + 1] << 16);
    }
    __syncthreads();
    {
        u32* dst = gPu + blockIdx.x * 4096;
        #pragma unroll
        for (int j = 0; j < 32; j++) {
            int v = j * 128 + t;
            dst[v] = stage[(v >> 5) * 33 + (v & 31)];
        }
    }
    __syncthreads();

    // ---- Q row ----
    {
        const float* mpp = mp + 3 * (size_t)i;
        const float* tgp = tg + 3 * (size_t)i;
        float m0 = mpp[0], m1 = mpp[1], m2 = mpp[2];
        float g0 = tgp[0], g1 = tgp[1], g2 = tgp[2];
        float Q[17];
        Q[0] = 1.0f;
        Q[1] = m0 * m0 + m1 * m1 + m2 * m2 + g0 * g0 + g1 * g1 + g2 * g2;
        Q[2] = g0; Q[3] = g1; Q[4] = g2;
        Q[5] = m0; Q[6] = m1; Q[7] = m2;
        Q[8]  = m0 * g0; Q[9]  = m0 * g1; Q[10] = m0 * g2;
        Q[11] = m1 * g0; Q[12] = m1 * g1; Q[13] = m1 * g2;
        Q[14] = m2 * g0; Q[15] = m2 * g1; Q[16] = m2 * g2;

        u16 col[64];
        #pragma unroll
        for (int k = 0; k < 64; k++) col[k] = 0;
        #pragma unroll
        for (int k = 0; k < 17; k++) {
            u16 h, l; split_bf16(Q[k], h, l);
            col[k] = h; col[17 + k] = l; col[34 + k] = h;
        }
        #pragma unroll
        for (int j = 0; j < 32; j++)
            stage[t * 33 + j] = (u32)col[2 * j] | ((u32)col[2 * j + 1] << 16);
    }
    __syncthreads();
    {
        u32* dst = gQu + blockIdx.x * 4096;
        #pragma unroll
        for (int j = 0; j < 32; j++) {
            int v = j * 128 + t;
            dst[v] = stage[(v >> 5) * 33 + (v & 31)];
        }
    }
}

// ---------------- K1: HMMA main kernel ----------------
// grid (2 nhalf, 16 mtile, 32 b), 128 thr = 4 warps, each warp one m16 tile.
// smem: P tile 64x64 bf16 (8KB) + Q chunk 128x64 bf16 (16KB), row%8 16B-xor swizzle.
__global__ void __launch_bounds__(128) k_main() {
    __shared__ u32 smA[2048];
    __shared__ u32 smB[4096];
    const int nh = blockIdx.x;
    const int mt = blockIdx.y;
    const int b  = blockIdx.z;
    const int t  = threadIdx.x;
    const int w  = t >> 5;
    const int lane = t & 31;
    const u32 aA = smem_u32(smA);
    const u32 aB = smem_u32(smB);

    // ---- load P tile (64 rows x 32 u32), swizzled ----
    {
        const u32* src = gPu + ((size_t)(b * MM + mt * 64)) * 32;
        #pragma unroll
        for (int j = 0; j < 16; j++) {
            int u = j * 128 + t;
            int row = u >> 5, c4 = u & 31;
            u32 sw = (u32)(row * 128 + c4 * 4) ^ (u32)((row & 7) << 4);
            smA[sw >> 2] = src[u];
        }
    }
    __syncthreads();

    // ---- A fragments: warp's m16 tile, 4 k-steps ----
    u32 afr[4][4];
    {
        int rowl = w * 16 + (lane & 7) + (((lane >> 3) & 1) << 3);
        int csel = lane >> 4;
        u32 rx = (u32)((rowl & 7) << 4);
        #pragma unroll
        for (int K = 0; K < 4; K++) {
            u32 off = ((u32)(rowl * 128 + (K * 2 + csel) * 16)) ^ rx;
            ldsm_x4(afr[K][0], afr[K][1], afr[K][2], afr[K][3], aA + off);
        }
    }

    float accL = 0.0f, accH = 0.0f;

    for (int ch = 0; ch < 4; ch++) {
        __syncthreads();
        // fill Q chunk (128 rows)
        {
            const u32* src = gQu + ((size_t)(b * NN + nh * 512 + ch * 128)) * 32;
            #pragma unroll
            for (int j = 0; j < 32; j++) {
                int u = j * 128 + t;
                int row = u >> 5, c4 = u & 31;
                u32 sw = (u32)(row * 128 + c4 * 4) ^ (u32)((row & 7) << 4);
                smB[sw >> 2] = src[u];
            }
        }
        __syncthreads();

        int l4 = lane & 15;
        int brow = l4 & 7;
        int bcsel = l4 >> 3;
        u32 rx = (u32)(brow << 4);
        #pragma unroll 2
        for (int T = 0; T < 16; T++) {
            u32 bfr[4][2];
            int rowl = T * 8 + brow;
            #pragma unroll
            for (int K = 0; K < 4; K++) {
                u32 off = ((u32)(rowl * 128 + (K * 2 + bcsel) * 16)) ^ rx;
                ldsm_x2(bfr[K][0], bfr[K][1], aB + off);
            }
            float d0 = 0.f, d1 = 0.f, d2 = 0.f, d3 = 0.f;
            #pragma unroll
            for (int K = 0; K < 4; K++)
                mma16816(d0, d1, d2, d3,
                         afr[K][0], afr[K][1], afr[K][2], afr[K][3],
                         bfr[K][0], bfr[K][1]);
            accL += sqrt_approx(fmaxf(d0, 0.f)) + sqrt_approx(fmaxf(d1, 0.f));
            accH += sqrt_approx(fmaxf(d2, 0.f)) + sqrt_approx(fmaxf(d3, 0.f));
        }
    }

    // ---- quad reduce (cols distributed over 4 lanes of each group) ----
    accL += __shfl_xor_sync(0xffffffffu, accL, 1);
    accL += __shfl_xor_sync(0xffffffffu, accL, 2);
    accH += __shfl_xor_sync(0xffffffffu, accH, 1);
    accH += __shfl_xor_sync(0xffffffffu, accH, 2);
    if ((lane & 3) == 0) {
        int row = mt * 64 + w * 16 + (lane >> 2);
        g_part[nh][b * MM + row]     = accL;
        g_part[nh][b * MM + row + 8] = accH;
    }
}

// ---------------- K2: combine + loss partials + argmax/R_best ----------------
__global__ void k_combine(const float* __restrict__ wptr,
                          const float* __restrict__ pred_r,
                          const float* __restrict__ pred_t,
                          const float* __restrict__ pred_c,
                          const float* __restrict__ points) {
    if (blockIdx.x >= 256) {
        int b = blockIdx.x - 256;
        int t = threadIdx.x;
        __shared__ float sv[128];
        __shared__ int   si[128];
        float cmax = -1e30f; int cidx = 0;
        #pragma unroll
        for (int k = 0; k < 8; k++) {                 // increasing m -> first-max tie-break
            int m = t + k * 128;
            float c = fmaxf(pred_c[b * MM + m], 1e-6f);
            if (c > cmax) { cmax = c; cidx = m; }
        }
        sv[t] = cmax; si[t] = cidx;
        __syncthreads();
        #pragma unroll
        for (int off = 64; off > 0; off >>= 1) {
            if (t < off) {
                if (sv[t + off] > sv[t] || (sv[t + off] == sv[t] && si[t + off] < si[t])) {
                    sv[t] = sv[t + off]; si[t] = si[t + off];
                }
            }
            __syncthreads();
        }
        if (t == 0) {
            int which = si[0];
            g_which[b] = which;
            int i = b * MM + which;
            float4 q = reinterpret_cast<const float4*>(pred_r)[i];
            float t0 = points[3 * i + 0] + pred_t[3 * i + 0];
            float t1 = points[3 * i + 1] + pred_t[3 * i + 1];
            float t2 = points[3 * i + 2] + pred_t[3 * i + 2];
            float o[12];
            quat_to_Rt(q.x, q.y, q.z, q.w, t0, t1, t2, o);
            #pragma unroll
            for (int j = 0; j < 12; j++) g_Rbest[b][j] = o[j];
        }
        return;
    }
    int i = blockIdx.x * 128 + threadIdx.x;
    float w = *wptr;
    float dsum = g_part[0][i] + g_part[1][i];
    g_dish[i] = dsum;
    float c = fmaxf(pred_c[i], 1e-6f);
    float term = dsum * (1.0f / (float)NN) * c - w * __logf(c);

    __shared__ float sbuf[128];
    int t = threadIdx.x;
    sbuf[t] = term;
    __syncthreads();
    #pragma unroll
    for (int off = 64; off > 0; off >>= 1) {
        if (t < off) sbuf[t] += sbuf[t + off];
        __syncthreads();
    }
    if (t == 0) g_lpart[blockIdx.x] = sbuf[0];
}

// ---------------- K3: transform + final scalars ----------------
__global__ void k_transform(const float* __restrict__ points,
                            const float* __restrict__ target,
                            float* __restrict__ out) {
    if (blockIdx.x == 256) {
        int t = threadIdx.x;
        __shared__ float sbuf[256];
        __shared__ float sdb;
        sbuf[t] = g_lpart[t];
        if (t < 32) {
            float db = g_dish[t * MM + g_which[t]];
            #pragma unroll
            for (int off = 16; off > 0; off >>= 1)
                db += __shfl_down_sync(0xffffffffu, db, off);
            if (t == 0) sdb = db;
        }
        __syncthreads();
        #pragma unroll
        for (int off = 128; off > 0; off >>= 1) {
            if (t < off) sbuf[t] += sbuf[t + off];
            __syncthreads();
        }
        if (t == 0) {
            out[0] = sbuf[0] / (float)(BB * MM);
            out[1] = sdb * (1.0f / (float)NN) / (float)BB;
        }
        return;
    }
    int id = blockIdx.x * 256 + threadIdx.x;
    int b = id >> 11;
    int r = id & 2047;

    const float4* rb4 = reinterpret_cast<const float4*>(&g_Rbest[b][0]);
    float4 ra = rb4[0], rbv = rb4[1], rc = rb4[2];
    float R0 = ra.x, R1 = ra.y, R2 = ra.z, R3 = ra.w;
    float R4 = rbv.x, R5 = rbv.y, R6 = rbv.z, R7 = rbv.w;
    float R8 = rc.x,  T0 = rc.y,  T1 = rc.z,  T2 = rc.w;

    const float* src;
    float* dst;
    if (r < MM) {
        src = points + ((size_t)b * MM + r) * 3;
        dst = out + 2 + ((size_t)b * MM + r) * 3;
    } else {
        int n = r - MM;
        src = target + ((size_t)b * NN + n) * 3;
        dst = out + 2 + (size_t)BB * MM * 3 + ((size_t)b * NN + n) * 3;
    }
    float d0 = src[0] - T0;
    float d1 = src[1] - T1;
    float d2 = src[2] - T2;
    dst[0] = d0 * R0 + d1 * R3 + d2 * R6;
    dst[1] = d0 * R1 + d1 * R4 + d2 * R7;
    dst[2] = d0 * R2 + d1 * R5 + d2 * R8;
}

// ---------------- launch ----------------
extern "C" void kernel_launch(void* const* d_in, const int* in_sizes, int n_in,
                              void* d_out, int out_size) {
    const float* pred_r       = (const float*)d_in[0];
    const float* pred_t       = (const float*)d_in[1];
    const float* pred_c       = (const float*)d_in[2];
    const float* target       = (const float*)d_in[3];
    const float* model_points = (const float*)d_in[4];
    // d_in[5] = idx (unused, refine path)
    const float* points       = (const float*)d_in[6];
    const float* wptr         = (const float*)d_in[7];
    // d_in[8] = refine (unused)
    float* out = (float*)d_out;

    k_prep<<<256, 128>>>(pred_r, pred_t, points, model_points, target);
    k_main<<<dim3(2, 16, BB), 128>>>();
    k_combine<<<288, 128>>>(wptr, pred_r, pred_t, pred_c, points);
    k_transform<<<257, 256>>>(points, target, out);
}